// round 1
// baseline (speedup 1.0000x reference)
#include <cuda_runtime.h>

#define FULL 0xffffffffu

__device__ __forceinline__ float2 cmulf(float2 a, float2 b) {
    return make_float2(a.x * b.x - a.y * b.y, a.x * b.y + a.y * b.x);
}

// Controlled rotation (RX if ISRX else RY) with control bit PC, target bit PT
// (bit positions in the 8-bit state index; index s = k*32 + lane,
//  lane holds bits 0..4, k holds bits 5..7).
template <int PC, int PT, bool ISRX>
__device__ __forceinline__ void cgate(float (&ar)[8], float (&ai)[8],
                                      float c, float s, int lane) {
    const bool ctrlLane = (PC <= 4) ? (((lane >> PC) & 1) != 0) : true;
    if (PT >= 5) {
        // target bit lives in k: local pairing
        const int tb = 1 << (PT - 5);
#pragma unroll
        for (int k = 0; k < 8; ++k) {
            if (k & tb) continue;                           // visit pair once
            if (PC >= 5 && !((k >> (PC - 5)) & 1)) continue; // control in k: skip ctrl=0
            const int k1 = k | tb;
            float r0 = ar[k], i0 = ai[k], r1 = ar[k1], i1 = ai[k1];
            float nr0, ni0, nr1, ni1;
            if (ISRX) {
                nr0 = c * r0 + s * i1;  ni0 = c * i0 - s * r1;
                nr1 = c * r1 + s * i0;  ni1 = c * i1 - s * r0;
            } else {
                nr0 = c * r0 - s * r1;  ni0 = c * i0 - s * i1;
                nr1 = s * r0 + c * r1;  ni1 = s * i0 + c * i1;
            }
            if (ctrlLane) { ar[k] = nr0; ai[k] = ni0; ar[k1] = nr1; ai[k1] = ni1; }
        }
    } else {
        // target bit lives in lane: shuffle pairing (partner has same control bit)
        const int tbit = (lane >> PT) & 1;
#pragma unroll
        for (int k = 0; k < 8; ++k) {
            if (PC >= 5 && !((k >> (PC - 5)) & 1)) continue; // uniform skip: shfl stays converged
            float pr = __shfl_xor_sync(FULL, ar[k], 1 << PT);
            float pi = __shfl_xor_sync(FULL, ai[k], 1 << PT);
            float nr, ni;
            if (ISRX) {
                nr = c * ar[k] + s * pi;
                ni = c * ai[k] - s * pr;
            } else {
                float sg = tbit ? s : -s;
                nr = c * ar[k] + sg * pr;
                ni = c * ai[k] + sg * pi;
            }
            if (ctrlLane) { ar[k] = nr; ai[k] = ni; }
        }
    }
}

__global__ __launch_bounds__(128)
void quanv_kernel(const float* __restrict__ X, const float* __restrict__ W,
                  float* __restrict__ out, int bs) {
    const int warp = (blockIdx.x * blockDim.x + threadIdx.x) >> 5;
    const int lane = threadIdx.x & 31;
    if (warp >= bs) return;
    const float* __restrict__ x = X + (size_t)warp * 64;

    // ===== Phase 1: per-wire 2-vectors. Wire q handled (redundantly) by lanes with lane&7==q.
    // After H on |0>: (alpha,beta) = (r, r)
    const float Rv = 0.70710678118654752440f;
    float2 A = make_float2(Rv, 0.f), B = make_float2(Rv, 0.f);
    const int q = lane & 7;
#pragma unroll
    for (int i = 0; i < 9; ++i) {
        const int idx = q * 9 + i;
        const bool ok = (idx < 64);
        float th = ok ? x[idx] : 0.f;
        float c, s;
        __sincosf(0.5f * th, &s, &c);
        if (ok) {
            if ((i & 1) == 0) {
                // RZ: alpha *= (c - i s), beta *= (c + i s)
                A = cmulf(A, make_float2(c, -s));
                B = cmulf(B, make_float2(c, s));
            } else {
                // RY: [ c -s ; s c ] (complex amplitudes, real coefficients)
                float2 A2 = make_float2(c * A.x - s * B.x, c * A.y - s * B.y);
                float2 B2 = make_float2(s * A.x + c * B.x, s * A.y + c * B.y);
                A = A2; B = B2;
            }
        }
    }

    // broadcast all 8 wire vectors to every lane
    float2 wa[8], wb[8];
#pragma unroll
    for (int w8 = 0; w8 < 8; ++w8) {
        wa[w8].x = __shfl_sync(FULL, A.x, w8);
        wa[w8].y = __shfl_sync(FULL, A.y, w8);
        wb[w8].x = __shfl_sync(FULL, B.x, w8);
        wb[w8].y = __shfl_sync(FULL, B.y, w8);
    }

    // ===== Build product state: amplitude index s = k*32 + lane,
    // wire q <-> bit (7-q); wires 3..7 -> lane bits 4..0, wires 0..2 -> k bits 2..0.
    float2 lp = ((lane >> 4) & 1) ? wb[3] : wa[3];
    lp = cmulf(lp, ((lane >> 3) & 1) ? wb[4] : wa[4]);
    lp = cmulf(lp, ((lane >> 2) & 1) ? wb[5] : wa[5]);
    lp = cmulf(lp, ((lane >> 1) & 1) ? wb[6] : wa[6]);
    lp = cmulf(lp, ((lane >> 0) & 1) ? wb[7] : wa[7]);

    float ar[8], ai[8];
#pragma unroll
    for (int k = 0; k < 8; ++k) {
        float2 kp = (k & 4) ? wb[0] : wa[0];
        kp = cmulf(kp, (k & 2) ? wb[1] : wa[1]);
        kp = cmulf(kp, (k & 1) ? wb[2] : wa[2]);
        float2 v = cmulf(kp, lp);
        ar[k] = v.x;
        ai[k] = v.y;
    }

    // ===== Phase 2: entangling layers. weights[l,i] at W[l*16+i]; lane j<16 holds sincos.
    {
        const int wl = lane >> 3, wi = lane & 7;
        float wangle = (lane < 16) ? W[wl * 16 + wi] : 0.f;
        float cw, sw;
        __sincosf(0.5f * wangle, &sw, &cw);

#define CG(L, CI, PC, PT, RX)                                           \
        {                                                               \
            float c_ = __shfl_sync(FULL, cw, (L) * 8 + (CI));           \
            float s_ = __shfl_sync(FULL, sw, (L) * 8 + (CI));           \
            cgate<PC, PT, RX>(ar, ai, c_, s_, lane);                    \
        }
        // layer 0: RX ((l+1)%2 != 0); control ci -> pc=7-ci, target (ci+1)%8 -> pt
        CG(0, 0, 7, 6, true)  CG(0, 1, 6, 5, true)  CG(0, 2, 5, 4, true)
        CG(0, 3, 4, 3, true)  CG(0, 4, 3, 2, true)  CG(0, 5, 2, 1, true)
        CG(0, 6, 1, 0, true)  CG(0, 7, 0, 7, true)
        // layer 1: RY
        CG(1, 0, 7, 6, false) CG(1, 1, 6, 5, false) CG(1, 2, 5, 4, false)
        CG(1, 3, 4, 3, false) CG(1, 4, 3, 2, false) CG(1, 5, 2, 1, false)
        CG(1, 6, 1, 0, false) CG(1, 7, 0, 7, false)
#undef CG
    }

    // ===== Measurement: out[b,q] = P(bit_{7-q}=0) - P(bit_{7-q}=1)
    float p[8], sumP = 0.f;
#pragma unroll
    for (int k = 0; k < 8; ++k) {
        p[k] = ar[k] * ar[k] + ai[k] * ai[k];
        sumP += p[k];
    }
    float o[8];
    o[0] = 0.f; o[1] = 0.f; o[2] = 0.f;
#pragma unroll
    for (int k = 0; k < 8; ++k) {
        o[0] += (k & 4) ? -p[k] : p[k];
        o[1] += (k & 2) ? -p[k] : p[k];
        o[2] += (k & 1) ? -p[k] : p[k];
    }
    o[3] = ((lane >> 4) & 1) ? -sumP : sumP;
    o[4] = ((lane >> 3) & 1) ? -sumP : sumP;
    o[5] = ((lane >> 2) & 1) ? -sumP : sumP;
    o[6] = ((lane >> 1) & 1) ? -sumP : sumP;
    o[7] = (lane & 1) ? -sumP : sumP;

#pragma unroll
    for (int qq = 0; qq < 8; ++qq) {
#pragma unroll
        for (int off = 16; off; off >>= 1)
            o[qq] += __shfl_xor_sync(FULL, o[qq], off);
    }

    if (lane == 0) {
        float4* po = (float4*)(out + (size_t)warp * 8);
        po[0] = make_float4(o[0], o[1], o[2], o[3]);
        po[1] = make_float4(o[4], o[5], o[6], o[7]);
    }
}

extern "C" void kernel_launch(void* const* d_in, const int* in_sizes, int n_in,
                              void* d_out, int out_size) {
    const float* X = (const float*)d_in[0];
    const float* W = (const float*)d_in[1];
    float* out = (float*)d_out;
    const int bs = in_sizes[0] / 64;
    const int threads = 128;
    const int wpb = threads / 32;
    const int blocks = (bs + wpb - 1) / wpb;
    quanv_kernel<<<blocks, threads>>>(X, W, out, bs);
}

// round 2
// speedup vs baseline: 1.0992x; 1.0992x over previous
#include <cuda_runtime.h>

#define FULL 0xffffffffu
typedef unsigned long long u64;

__device__ __forceinline__ u64 pk2(float x, float y) {
    u64 r; asm("mov.b64 %0,{%1,%2};" : "=l"(r) : "f"(x), "f"(y)); return r;
}
__device__ __forceinline__ void upk2(u64 v, float& x, float& y) {
    asm("mov.b64 {%0,%1},%2;" : "=f"(x), "=f"(y) : "l"(v));
}
__device__ __forceinline__ u64 fma2_(u64 a, u64 b, u64 c) {
    u64 d; asm("fma.rn.f32x2 %0,%1,%2,%3;" : "=l"(d) : "l"(a), "l"(b), "l"(c)); return d;
}
__device__ __forceinline__ u64 mul2_(u64 a, u64 b) {
    u64 d; asm("mul.rn.f32x2 %0,%1,%2;" : "=l"(d) : "l"(a), "l"(b)); return d;
}
__device__ __forceinline__ float2 cmulf(float2 a, float2 b) {
    return make_float2(a.x * b.x - a.y * b.y, a.x * b.y + a.y * b.x);
}

// Controlled rotation (RX if ISRX else RY), control bit PC, target bit PT.
// State index s = k*32 + lane; lane holds bits 0..4, k holds bits 5..7.
// Control is folded into coefficients (no predicated writes).
template <int PC, int PT, bool ISRX>
__device__ __forceinline__ void cgate(u64 (&v)[8], float c, float s, int lane) {
    float cE, sE;
    if (PC <= 4) {
        const bool ctrl = ((lane >> PC) & 1) != 0;
        cE = ctrl ? c : 1.0f;
        sE = ctrl ? s : 0.0f;
    } else { cE = c; sE = s; }

    if (PT >= 5) {
        // target bit in k: local pairing
        const int tb = 1 << (PT - 5);
        const u64 cc = pk2(cE, cE);
#pragma unroll
        for (int k = 0; k < 8; ++k) {
            if (k & tb) continue;
            if (PC >= 5 && !((k >> (PC - 5)) & 1)) continue;
            const int k1 = k | tb;
            float r0, i0, r1, i1;
            upk2(v[k], r0, i0);
            upk2(v[k1], r1, i1);
            if (ISRX) {
                const u64 sn = pk2(sE, -sE);
                v[k]  = fma2_(cc, v[k],  mul2_(sn, pk2(i1, r1)));
                v[k1] = fma2_(cc, v[k1], mul2_(sn, pk2(i0, r0)));
            } else {
                const u64 ssn = pk2(-sE, -sE);
                const u64 ssp = pk2(sE, sE);
                const u64 old0 = v[k];
                v[k]  = fma2_(cc, v[k],  mul2_(ssn, v[k1]));
                v[k1] = fma2_(cc, v[k1], mul2_(ssp, old0));
            }
        }
    } else {
        // target bit in lane: shuffle pairing
        const int m = 1 << PT;
        const u64 cc = pk2(cE, cE);
        u64 smul;
        if (ISRX) {
            smul = pk2(sE, -sE);
        } else {
            const float sg = ((lane >> PT) & 1) ? sE : -sE;
            smul = pk2(sg, sg);
        }
#pragma unroll
        for (int k = 0; k < 8; ++k) {
            if (PC >= 5 && !((k >> (PC - 5)) & 1)) continue;  // uniform skip
            float r, i;
            upk2(v[k], r, i);
            const float pr = __shfl_xor_sync(FULL, r, m);
            const float pi = __shfl_xor_sync(FULL, i, m);
            const u64 p = ISRX ? pk2(pi, pr) : pk2(pr, pi);
            v[k] = fma2_(cc, v[k], mul2_(smul, p));
        }
    }
}

__global__ __launch_bounds__(128)
void quanv_kernel(const float* __restrict__ X, const float* __restrict__ W,
                  float* __restrict__ out, int bs) {
    const int warp = (blockIdx.x * blockDim.x + threadIdx.x) >> 5;
    const int lane = threadIdx.x & 31;
    if (warp >= bs) return;
    const float* __restrict__ x = X + (size_t)warp * 64;

    // ===== Phase 1: per-wire 2-vectors; wire q = lane&7, groups redundant.
    const float Rv = 0.70710678118654752440f;
    float2 A = make_float2(Rv, 0.f), B = make_float2(Rv, 0.f);
    const int q = lane & 7;
#pragma unroll
    for (int i = 0; i < 9; ++i) {
        const int idx = q * 9 + i;
        const bool ok = (idx < 64);
        const float th = x[ok ? idx : 0];
        float c, s;
        __sincosf(0.5f * th, &s, &c);
        if (ok) {
            if ((i & 1) == 0) {
                A = cmulf(A, make_float2(c, -s));
                B = cmulf(B, make_float2(c, s));
            } else {
                float2 A2 = make_float2(c * A.x - s * B.x, c * A.y - s * B.y);
                float2 B2 = make_float2(s * A.x + c * B.x, s * A.y + c * B.y);
                A = A2; B = B2;
            }
        }
    }

    // Slim broadcast: lanes with (lane&8)==0 present A, else B.
    // A_w at source lane w, B_w at source lane 8+w.
    float2 V = (lane & 8) ? B : A;

    // lp = product of selected vectors for wires 3..7 (lane bits 4..0)
    float2 lp;
    {
        const int b = (lane >> 4) & 1;
        const int src = (b << 3) | 3;
        lp.x = __shfl_sync(FULL, V.x, src);
        lp.y = __shfl_sync(FULL, V.y, src);
    }
#pragma unroll
    for (int w = 4; w < 8; ++w) {
        const int b = (lane >> (7 - w)) & 1;
        const int src = (b << 3) | w;
        float2 t;
        t.x = __shfl_sync(FULL, V.x, src);
        t.y = __shfl_sync(FULL, V.y, src);
        lp = cmulf(lp, t);
    }
    // wires 0..2: need both components
    float2 a0, b0, a1, b1, a2, b2;
    a0.x = __shfl_sync(FULL, V.x, 0);  a0.y = __shfl_sync(FULL, V.y, 0);
    b0.x = __shfl_sync(FULL, V.x, 8);  b0.y = __shfl_sync(FULL, V.y, 8);
    a1.x = __shfl_sync(FULL, V.x, 1);  a1.y = __shfl_sync(FULL, V.y, 1);
    b1.x = __shfl_sync(FULL, V.x, 9);  b1.y = __shfl_sync(FULL, V.y, 9);
    a2.x = __shfl_sync(FULL, V.x, 2);  a2.y = __shfl_sync(FULL, V.y, 2);
    b2.x = __shfl_sync(FULL, V.x, 10); b2.y = __shfl_sync(FULL, V.y, 10);

    // Build product state with shared subproducts.
    float2 c01[4];
    c01[0] = cmulf(a0, a1);
    c01[1] = cmulf(a0, b1);
    c01[2] = cmulf(b0, a1);
    c01[3] = cmulf(b0, b1);
    float2 d01[4];
#pragma unroll
    for (int j = 0; j < 4; ++j) d01[j] = cmulf(c01[j], lp);

    u64 v[8];
#pragma unroll
    for (int k = 0; k < 8; ++k) {
        const float2 t = cmulf(d01[k >> 1], (k & 1) ? b2 : a2);
        v[k] = pk2(t.x, t.y);
    }

    // ===== Phase 2: entangling layers.
    {
        const int wl = lane >> 3, wi = lane & 7;
        const float wangle = (lane < 16) ? W[wl * 16 + wi] : 0.f;
        float cw, sw;
        __sincosf(0.5f * wangle, &sw, &cw);

#define CG(L, CI, PC, PT, RX)                                        \
        {                                                            \
            const float c_ = __shfl_sync(FULL, cw, (L) * 8 + (CI));  \
            const float s_ = __shfl_sync(FULL, sw, (L) * 8 + (CI));  \
            cgate<PC, PT, RX>(v, c_, s_, lane);                      \
        }
        CG(0, 0, 7, 6, true)  CG(0, 1, 6, 5, true)  CG(0, 2, 5, 4, true)
        CG(0, 3, 4, 3, true)  CG(0, 4, 3, 2, true)  CG(0, 5, 2, 1, true)
        CG(0, 6, 1, 0, true)  CG(0, 7, 0, 7, true)
        CG(1, 0, 7, 6, false) CG(1, 1, 6, 5, false) CG(1, 2, 5, 4, false)
        CG(1, 3, 4, 3, false) CG(1, 4, 3, 2, false) CG(1, 5, 2, 1, false)
        CG(1, 6, 1, 0, false) CG(1, 7, 0, 7, false)
#undef CG
    }

    // ===== Measurement
    float p[8];
#pragma unroll
    for (int k = 0; k < 8; ++k) {
        float x2, y2;
        upk2(mul2_(v[k], v[k]), x2, y2);
        p[k] = x2 + y2;
    }
    const float s01 = p[0] + p[1], s23 = p[2] + p[3];
    const float s45 = p[4] + p[5], s67 = p[6] + p[7];
    const float e0 = s01 + s23, e1 = s45 + s67;
    const float sumP = e0 + e1;
    float o0 = e0 - e1;
    float o1 = (s01 - s23) + (s45 - s67);
    float o2 = (p[0] - p[1]) + (p[2] - p[3]) + (p[4] - p[5]) + (p[6] - p[7]);

    // Walsh-Hadamard butterfly on sumP: lane L ends with
    // sum_j (-1)^{popc(L&j)} sumP_j  -> o3..o7 live at lanes 16,8,4,2,1.
    float wv = sumP;
#pragma unroll
    for (int st = 0; st < 5; ++st) {
        const int m = 1 << st;
        const float pg = __shfl_xor_sync(FULL, wv, m);
        const float sg = (lane & m) ? -1.f : 1.f;
        wv = fmaf(wv, sg, pg);
    }

    // Plain sums for o0..o2
#pragma unroll
    for (int m = 16; m; m >>= 1) {
        o0 += __shfl_xor_sync(FULL, o0, m);
        o1 += __shfl_xor_sync(FULL, o1, m);
        o2 += __shfl_xor_sync(FULL, o2, m);
    }

    const float o3 = __shfl_sync(FULL, wv, 16);
    const float o4 = __shfl_sync(FULL, wv, 8);
    const float o5 = __shfl_sync(FULL, wv, 4);
    const float o6 = __shfl_sync(FULL, wv, 2);
    const float o7 = __shfl_sync(FULL, wv, 1);

    if (lane == 0) {
        float4* po = (float4*)(out + (size_t)warp * 8);
        po[0] = make_float4(o0, o1, o2, o3);
        po[1] = make_float4(o4, o5, o6, o7);
    }
}

extern "C" void kernel_launch(void* const* d_in, const int* in_sizes, int n_in,
                              void* d_out, int out_size) {
    const float* X = (const float*)d_in[0];
    const float* W = (const float*)d_in[1];
    float* out = (float*)d_out;
    const int bs = in_sizes[0] / 64;
    const int threads = 128;
    const int wpb = threads / 32;
    const int blocks = (bs + wpb - 1) / wpb;
    quanv_kernel<<<blocks, threads>>>(X, W, out, bs);
}

// round 3
// speedup vs baseline: 1.3433x; 1.2220x over previous
#include <cuda_runtime.h>

#define FULL 0xffffffffu
typedef unsigned long long u64;

__device__ __forceinline__ u64 pk2(float x, float y) {
    u64 r; asm("mov.b64 %0,{%1,%2};" : "=l"(r) : "f"(x), "f"(y)); return r;
}
__device__ __forceinline__ void upk2(u64 v, float& x, float& y) {
    asm("mov.b64 {%0,%1},%2;" : "=f"(x), "=f"(y) : "l"(v));
}
__device__ __forceinline__ u64 fma2_(u64 a, u64 b, u64 c) {
    u64 d; asm("fma.rn.f32x2 %0,%1,%2,%3;" : "=l"(d) : "l"(a), "l"(b), "l"(c)); return d;
}
__device__ __forceinline__ u64 mul2_(u64 a, u64 b) {
    u64 d; asm("mul.rn.f32x2 %0,%1,%2;" : "=l"(d) : "l"(a), "l"(b)); return d;
}
__device__ __forceinline__ float2 cmulf(float2 a, float2 b) {
    return make_float2(a.x * b.x - a.y * b.y, a.x * b.y + a.y * b.x);
}

// Layout: each half-warp (16 lanes) holds one batch element.
// State index s (8 bits): bits {7,5,3,1} -> k register index bits {3,2,1,0};
//                         bits {6,4,2,0} -> half-lane (hl) bits {3,2,1,0}.
// v[k] holds packed (re,im).

// Local gate: control in lane bit LB, target in k bit KB. Control folded
// into coefficients (no predicated writes).
template <int LB, int KB, bool ISRX>
__device__ __forceinline__ void gate_local(u64 (&v)[16], float c, float s, int hl) {
    const bool ctrl = ((hl >> LB) & 1) != 0;
    const float cE = ctrl ? c : 1.0f;
    const float sE = ctrl ? s : 0.0f;
    const u64 cc = pk2(cE, cE);
#pragma unroll
    for (int k = 0; k < 16; ++k) {
        if (k & (1 << KB)) continue;
        const int k1 = k | (1 << KB);
        if (ISRX) {
            const u64 sn = pk2(sE, -sE);
            float r0, i0, r1, i1;
            upk2(v[k], r0, i0);
            upk2(v[k1], r1, i1);
            v[k]  = fma2_(cc, v[k],  mul2_(sn, pk2(i1, r1)));
            v[k1] = fma2_(cc, v[k1], mul2_(sn, pk2(i0, r0)));
        } else {
            const u64 old0 = v[k];
            v[k]  = fma2_(cc, v[k],  mul2_(pk2(-sE, -sE), v[k1]));
            v[k1] = fma2_(cc, v[k1], mul2_(pk2(sE, sE), old0));
        }
    }
}

// Shuffle gate: control in k bit KB (skip ctrl=0 regs at compile time),
// target in lane bit LB (xor mask 1<<LB, stays within half-warp).
template <int KB, int LB, bool ISRX>
__device__ __forceinline__ void gate_shfl(u64 (&v)[16], float c, float s, int hl) {
    const u64 cc = pk2(c, c);
    u64 smul;
    if (ISRX) {
        smul = pk2(s, -s);
    } else {
        const float sg = ((hl >> LB) & 1) ? s : -s;
        smul = pk2(sg, sg);
    }
#pragma unroll
    for (int k = 0; k < 16; ++k) {
        if (!(k & (1 << KB))) continue;   // control bit = 0: identity
        float r, i;
        upk2(v[k], r, i);
        const float pr = __shfl_xor_sync(FULL, r, 1 << LB);
        const float pi = __shfl_xor_sync(FULL, i, 1 << LB);
        const u64 p = ISRX ? pk2(pi, pr) : pk2(pr, pi);
        v[k] = fma2_(cc, v[k], mul2_(smul, p));
    }
}

__global__ __launch_bounds__(128)
void quanv_kernel(const float* __restrict__ X, const float* __restrict__ W,
                  float* __restrict__ out, int bs) {
    const int warp = (blockIdx.x * blockDim.x + threadIdx.x) >> 5;
    const int lane = threadIdx.x & 31;
    const int e = lane >> 4;          // element within warp
    const int hl = lane & 15;         // half-lane
    const int half = lane & 16;       // half-warp base for shuffles
    const long elem = (long)warp * 2 + e;
    const bool valid = elem < bs;
    const float* __restrict__ x = X + (valid ? elem : 0) * 64;

    // ===== Phase 1: per-wire 2-vectors. wire q = lane&7 (lanes 8..15 duplicate).
    const float Rv = 0.70710678118654752440f;
    float2 A = make_float2(Rv, 0.f), B = make_float2(Rv, 0.f);
    const int q = lane & 7;
#pragma unroll
    for (int i = 0; i < 9; ++i) {
        const int idx = q * 9 + i;
        const bool ok = (idx < 64);
        const float th = x[ok ? idx : 0];
        float c, s;
        __sincosf(0.5f * th, &s, &c);
        if (ok) {
            if ((i & 1) == 0) {
                A = cmulf(A, make_float2(c, -s));
                B = cmulf(B, make_float2(c, s));
            } else {
                float2 A2 = make_float2(c * A.x - s * B.x, c * A.y - s * B.y);
                float2 B2 = make_float2(s * A.x + c * B.x, s * A.y + c * B.y);
                A = A2; B = B2;
            }
        }
    }
    // Within each half-warp: lane half+w presents A_w, lane half+8+w presents B_w.
    float2 V = (lane & 8) ? B : A;

    // lp: product over lane-held wires 1,3,5,7 (hl bits 3,2,1,0 select component).
    float2 lp;
    {
        const int b = (hl >> 3) & 1;
        const int src = half | (b << 3) | 1;
        lp.x = __shfl_sync(FULL, V.x, src);
        lp.y = __shfl_sync(FULL, V.y, src);
    }
    {
        const int b = (hl >> 2) & 1;
        const int src = half | (b << 3) | 3;
        float2 t;
        t.x = __shfl_sync(FULL, V.x, src);
        t.y = __shfl_sync(FULL, V.y, src);
        lp = cmulf(lp, t);
    }
    {
        const int b = (hl >> 1) & 1;
        const int src = half | (b << 3) | 5;
        float2 t;
        t.x = __shfl_sync(FULL, V.x, src);
        t.y = __shfl_sync(FULL, V.y, src);
        lp = cmulf(lp, t);
    }
    {
        const int b = hl & 1;
        const int src = half | (b << 3) | 7;
        float2 t;
        t.x = __shfl_sync(FULL, V.x, src);
        t.y = __shfl_sync(FULL, V.y, src);
        lp = cmulf(lp, t);
    }

    // k-held wires 0,2,4,6: both components.
    float2 w0[2], w2[2], w4[2], w6[2];
#pragma unroll
    for (int b = 0; b < 2; ++b) {
        w0[b].x = __shfl_sync(FULL, V.x, half | (b << 3) | 0);
        w0[b].y = __shfl_sync(FULL, V.y, half | (b << 3) | 0);
        w2[b].x = __shfl_sync(FULL, V.x, half | (b << 3) | 2);
        w2[b].y = __shfl_sync(FULL, V.y, half | (b << 3) | 2);
        w4[b].x = __shfl_sync(FULL, V.x, half | (b << 3) | 4);
        w4[b].y = __shfl_sync(FULL, V.y, half | (b << 3) | 4);
        w6[b].x = __shfl_sync(FULL, V.x, half | (b << 3) | 6);
        w6[b].y = __shfl_sync(FULL, V.y, half | (b << 3) | 6);
    }

    // Build product state: k = (w0bit<<3)|(w2bit<<2)|(w4bit<<1)|w6bit.
    u64 v[16];
    {
        float2 d8[8];
#pragma unroll
        for (int i = 0; i < 2; ++i)
#pragma unroll
            for (int j = 0; j < 2; ++j) {
                const float2 c02 = cmulf(cmulf(w0[i], w2[j]), lp);
#pragma unroll
                for (int n = 0; n < 2; ++n)
                    d8[(((i << 1) | j) << 1) | n] = cmulf(c02, w4[n]);
            }
#pragma unroll
        for (int k = 0; k < 16; ++k) {
            const float2 t = cmulf(d8[k >> 1], w6[k & 1]);
            v[k] = pk2(t.x, t.y);
        }
    }

    // ===== Phase 2: entangling layers. Weight sincos in lanes 0..15, shared by
    // both half-warps (weights are batch-independent).
    {
        const float wangle = (lane < 16) ? W[(lane >> 3) * 16 + (lane & 7)] : 0.f;
        float cw, sw;
        __sincosf(0.5f * wangle, &sw, &cw);

#define CGS(L, CI, KB, LB, RX)                                       \
        {                                                            \
            const float c_ = __shfl_sync(FULL, cw, (L) * 8 + (CI));  \
            const float s_ = __shfl_sync(FULL, sw, (L) * 8 + (CI));  \
            gate_shfl<KB, LB, RX>(v, c_, s_, hl);                    \
        }
#define CGL(L, CI, LB, KB, RX)                                       \
        {                                                            \
            const float c_ = __shfl_sync(FULL, cw, (L) * 8 + (CI));  \
            const float s_ = __shfl_sync(FULL, sw, (L) * 8 + (CI));  \
            gate_local<LB, KB, RX>(v, c_, s_, hl);                   \
        }
        // layer 0 (RX): gate i: control bit 7-i, target bit (6-i)%8-ish ring
        CGS(0, 0, 3, 3, true)   // (7,6)
        CGL(0, 1, 3, 2, true)   // (6,5)
        CGS(0, 2, 2, 2, true)   // (5,4)
        CGL(0, 3, 2, 1, true)   // (4,3)
        CGS(0, 4, 1, 1, true)   // (3,2)
        CGL(0, 5, 1, 0, true)   // (2,1)
        CGS(0, 6, 0, 0, true)   // (1,0)
        CGL(0, 7, 0, 3, true)   // (0,7)
        // layer 1 (RY)
        CGS(1, 0, 3, 3, false)
        CGL(1, 1, 3, 2, false)
        CGS(1, 2, 2, 2, false)
        CGL(1, 3, 2, 1, false)
        CGS(1, 4, 1, 1, false)
        CGL(1, 5, 1, 0, false)
        CGS(1, 6, 0, 0, false)
        CGL(1, 7, 0, 3, false)
#undef CGS
#undef CGL
    }

    // ===== Measurement
    float p[16];
#pragma unroll
    for (int k = 0; k < 16; ++k) {
        float x2, y2;
        upk2(mul2_(v[k], v[k]), x2, y2);
        p[k] = x2 + y2;
    }
    // Tree over k bits: bit0=wire6, bit1=wire4, bit2=wire2, bit3=wire0.
    float s1[8], ow6 = 0.f;
#pragma unroll
    for (int j = 0; j < 8; ++j) {
        s1[j] = p[2 * j] + p[2 * j + 1];
        ow6 += p[2 * j] - p[2 * j + 1];
    }
    float s2[4], ow4 = 0.f;
#pragma unroll
    for (int j = 0; j < 4; ++j) {
        s2[j] = s1[2 * j] + s1[2 * j + 1];
        ow4 += s1[2 * j] - s1[2 * j + 1];
    }
    const float s30 = s2[0] + s2[1], s31 = s2[2] + s2[3];
    float ow2 = (s2[0] - s2[1]) + (s2[2] - s2[3]);
    float ow0 = s30 - s31;
    float sumP = s30 + s31;

    // Butterfly reduce ow0/ow2/ow4/ow6 within half-warp.
#pragma unroll
    for (int m = 8; m; m >>= 1) {
        ow0 += __shfl_xor_sync(FULL, ow0, m);
        ow2 += __shfl_xor_sync(FULL, ow2, m);
        ow4 += __shfl_xor_sync(FULL, ow4, m);
        ow6 += __shfl_xor_sync(FULL, ow6, m);
    }
    // Walsh on sumP over hl bits: lane with single bit b set gets wire for that bit.
    float wv = sumP;
#pragma unroll
    for (int st = 0; st < 4; ++st) {
        const int m = 1 << st;
        const float pg = __shfl_xor_sync(FULL, wv, m);
        const float sg = (hl & m) ? -1.f : 1.f;
        wv = fmaf(wv, sg, pg);
    }
    const float ow1 = __shfl_sync(FULL, wv, half | 8);
    const float ow3 = __shfl_sync(FULL, wv, half | 4);
    const float ow5 = __shfl_sync(FULL, wv, half | 2);
    const float ow7 = __shfl_sync(FULL, wv, half | 1);

    if (hl == 0 && valid) {
        float4* po = (float4*)(out + elem * 8);
        po[0] = make_float4(ow0, ow1, ow2, ow3);
        po[1] = make_float4(ow4, ow5, ow6, ow7);
    }
}

extern "C" void kernel_launch(void* const* d_in, const int* in_sizes, int n_in,
                              void* d_out, int out_size) {
    const float* X = (const float*)d_in[0];
    const float* W = (const float*)d_in[1];
    float* out = (float*)d_out;
    const int bs = in_sizes[0] / 64;
    const int warps = (bs + 1) / 2;
    const int threads = 128;
    const int wpb = threads / 32;
    const int blocks = (warps + wpb - 1) / wpb;
    quanv_kernel<<<blocks, threads>>>(X, W, out, bs);
}